// round 4
// baseline (speedup 1.0000x reference)
#include <cuda_runtime.h>
#include <math.h>

#define B_    4
#define Q_    100
#define T_    8
#define G_    4
#define CG_   64
#define SP_   32
#define D_    256
#define BQ_   (B_*Q_)         // 400
#define PS_   8192
#define PT_   4352
#define NS_   (G_*PS_)        // 32768
#define NT_   (G_*PT_)        // 17408
#define CT_   (D_*T_)         // 2048

#define NSPLIT_S 32
#define NSPLIT_T 8

// ------------------ scratch (__device__ globals; no allocation allowed) ---
__device__ __align__(16) float g_ftr0[B_*64*64*CT_];
__device__ __align__(16) float g_ftr1[B_*32*32*CT_];
__device__ __align__(16) float g_ftr2[B_*16*16*CT_];
__device__ __align__(16) float g_ftr3[B_*8*8*CT_];
__device__ __align__(16) float g_off[BQ_*384];
__device__ __align__(16) float g_ps [BQ_*NS_];
__device__ __align__(16) float g_pt [BQ_*NT_];
__device__ __align__(16) float g_spat[BQ_*G_*SP_*CG_];
__device__ __align__(16) float g_temp[BQ_*G_*T_*CG_];
__device__ __align__(16) float g_mixs[BQ_*NS_];
__device__ __align__(16) float g_mixt[BQ_*G_*32*CG_];
__device__ __align__(16) float g_part_s[NSPLIT_S*BQ_*D_];
__device__ __align__(16) float g_part_t[NSPLIT_T*BQ_*D_];

// ------------------ block reduce (sum, sumsq), blockDim = 256 -------------
__device__ __forceinline__ void blockReduce2(float& s, float& q, float* red) {
    #pragma unroll
    for (int o = 16; o; o >>= 1) {
        s += __shfl_xor_sync(0xffffffffu, s, o);
        q += __shfl_xor_sync(0xffffffffu, q, o);
    }
    int w = threadIdx.x >> 5, lane = threadIdx.x & 31;
    if (lane == 0) { red[w] = s; red[8 + w] = q; }
    __syncthreads();
    if (w == 0) {
        s = red[lane & 7]; q = red[8 + (lane & 7)];
        #pragma unroll
        for (int o = 4; o; o >>= 1) {
            s += __shfl_xor_sync(0xffffffffu, s, o);
            q += __shfl_xor_sync(0xffffffffu, q, o);
        }
        if (lane == 0) { red[0] = s; red[1] = q; }
    }
    __syncthreads();
    s = red[0]; q = red[1];
    __syncthreads();
}

// ------------------ feature transpose: (b,c,t,y,x) -> (b,y,x,c,t) ---------
__global__ void k_transpose(const float* __restrict__ src, float* __restrict__ dst,
                            int H, int W) {
    __shared__ float tile[256][33];
    int tid = threadIdx.x;
    int xb = blockIdx.x * 32;
    int cb = blockIdx.y * 32;
    int b  = blockIdx.z / H, y = blockIdx.z % H;
    int x  = tid & 31;
    int sub = tid >> 5;
    if (xb + x < W) {
        #pragma unroll
        for (int i = 0; i < 32; i++) {
            int ct = i * 8 + sub;
            int c = cb + (ct >> 3), t = ct & 7;
            tile[ct][x] = src[(((b*D_ + c)*T_ + t)*H + y)*W + xb + x];
        }
    }
    __syncthreads();
    int xmax = W - xb; if (xmax > 32) xmax = 32;
    for (int xx = 0; xx < xmax; xx++) {
        dst[((b*H + y)*W + xb + xx)*CT_ + cb*8 + tid] = tile[tid][xx];
    }
}

// ------------------ tiled GEMM 128x64xBK32, 8x4/thread, split-K ----------
// C[split] (M x N) = A(M x K-slice) * W(K x N) [+ bias]
// Requires: N % 64 == 0, kc % 32 == 0, K % 4 == 0 (all call sites satisfy).
__global__ void __launch_bounds__(256)
k_gemm(const float* __restrict__ A, const float* __restrict__ Wm,
       const float* __restrict__ bias, float* __restrict__ Cbase,
       int M, int N, int K, int kc) {
    // Stride 132: multiple of 4 so every float4 read &As[k][8*ty] is 16B
    // aligned (132 % 4 == 0); the k*132 term keeps rows rotating banks.
    __shared__ float As[32][132];   // [k][m]
    __shared__ float Bs[32][64];    // [k][n]
    int split = blockIdx.z;
    int k0 = split * kc;
    float* C = Cbase + (size_t)split * M * N;
    int tid = threadIdx.x;
    int m0 = blockIdx.y * 128, n0 = blockIdx.x * 64;
    int tx = tid & 15, ty = tid >> 4;           // 16 x 16 thread grid
    int arow = tid >> 3, akq = tid & 7;         // A: float4 per (row, kq)
    int bk = tid >> 4, bnq = tid & 15;          // B: float4 per (k, nq)
    float acc[8][4] = {};
    for (int kk = k0; kk < k0 + kc; kk += 32) {
        #pragma unroll
        for (int r = 0; r < 4; r++) {
            int row = arow + r * 32;            // 0..127
            int m = m0 + row;
            float4 v = make_float4(0.f, 0.f, 0.f, 0.f);
            if (m < M) v = *(const float4*)(A + (size_t)m*K + kk + akq*4);
            As[akq*4 + 0][row] = v.x;
            As[akq*4 + 1][row] = v.y;
            As[akq*4 + 2][row] = v.z;
            As[akq*4 + 3][row] = v.w;
        }
        #pragma unroll
        for (int r = 0; r < 2; r++) {
            int k = bk + r * 16;                // 0..31
            *(float4*)(&Bs[k][bnq*4]) =
                *(const float4*)(Wm + (size_t)(kk + k)*N + n0 + bnq*4);
        }
        __syncthreads();
        #pragma unroll
        for (int k = 0; k < 32; k++) {
            float a[8], bb[4];
            float4 a0 = *(const float4*)(&As[k][ty*8]);
            float4 a1 = *(const float4*)(&As[k][ty*8 + 4]);
            a[0]=a0.x; a[1]=a0.y; a[2]=a0.z; a[3]=a0.w;
            a[4]=a1.x; a[5]=a1.y; a[6]=a1.z; a[7]=a1.w;
            float4 b0 = *(const float4*)(&Bs[k][tx*4]);
            bb[0]=b0.x; bb[1]=b0.y; bb[2]=b0.z; bb[3]=b0.w;
            #pragma unroll
            for (int i = 0; i < 8; i++)
                #pragma unroll
                for (int j = 0; j < 4; j++)
                    acc[i][j] += a[i] * bb[j];
        }
        __syncthreads();
    }
    #pragma unroll
    for (int i = 0; i < 8; i++) {
        int m = m0 + ty*8 + i;
        if (m < M) {
            int n = n0 + tx*4;
            float4 o;
            o.x = acc[i][0]; o.y = acc[i][1]; o.z = acc[i][2]; o.w = acc[i][3];
            if (bias) {
                o.x += bias[n]; o.y += bias[n+1]; o.z += bias[n+2]; o.w += bias[n+3];
            }
            *(float4*)(C + (size_t)m*N + n) = o;
        }
    }
}

// ------------------ bilinear sampling + T-mean / SP-mean fusion ----------
__global__ void __launch_bounds__(256)
k_sample(const float* __restrict__ boxes) {
    __shared__ float spx[SP_][4], spy[SP_][4], slw[SP_][4];
    int blk = blockIdx.x;            // bq*4 + g
    int g  = blk & 3;
    int bq = blk >> 2;
    int b  = bq / Q_;
    int tid = threadIdx.x;
    const float* pb = boxes + bq * 4;
    float cx = pb[0], cy = pb[1], zb = pb[2], rb = pb[3];
    if (tid < 128) {
        int sp = tid >> 2, l = tid & 3;
        const float* po = g_off + bq*384 + (g*SP_ + sp)*3;
        float X = cx + po[0] * exp2f(zb - 0.5f*rb);
        float Y = cy + po[1] * exp2f(zb + 0.5f*rb);
        float mapped = zb + po[2] - 2.0f;     // z - log2(4)
        float dl = mapped - (float)l;
        float e = __expf(-0.5f * dl * dl);
        float s = e;
        s += __shfl_xor_sync(0xffffffffu, s, 1);
        s += __shfl_xor_sync(0xffffffffu, s, 2);
        float inv_stride = 1.0f / (float)(4 << l);
        spx[sp][l] = X * inv_stride - 0.5f;
        spy[sp][l] = Y * inv_stride - 0.5f;
        slw[sp][l] = e / s;
    }
    __syncthreads();

    int cg = tid >> 2, tg = tid & 3;          // thread owns t = 2*tg, 2*tg+1
    int coff = g*(CG_*T_) + cg*T_ + 2*tg;
    float tacc0 = 0.f, tacc1 = 0.f;
    for (int sp = 0; sp < SP_; sp++) {
        float sacc = 0.f;
        #pragma unroll
        for (int l = 0; l < 4; l++) {
            const float* F; int H;
            if      (l == 0) { F = g_ftr0; H = 64; }
            else if (l == 1) { F = g_ftr1; H = 32; }
            else if (l == 2) { F = g_ftr2; H = 16; }
            else             { F = g_ftr3; H = 8;  }
            float w  = slw[sp][l];
            float px = spx[sp][l], py = spy[sp][l];
            float x0f = floorf(px), y0f = floorf(py);
            float fx = px - x0f, fy = py - y0f;
            int x0 = (int)x0f, y0 = (int)y0f;
            #pragma unroll
            for (int tap = 0; tap < 4; tap++) {
                int dx = tap & 1, dy = tap >> 1;
                int xi = x0 + dx, yi = y0 + dy;
                if (xi < 0 || xi >= H || yi < 0 || yi >= H) continue;
                float wt = w * (dx ? fx : 1.f - fx) * (dy ? fy : 1.f - fy);
                const float2* p = (const float2*)(F + ((b*H + yi)*H + xi)*CT_ + coff);
                float2 v = *p;
                tacc0 += wt * v.x;
                tacc1 += wt * v.y;
                sacc  += wt * (v.x + v.y);
            }
        }
        sacc += __shfl_xor_sync(0xffffffffu, sacc, 1);
        sacc += __shfl_xor_sync(0xffffffffu, sacc, 2);
        if (tg == 0) g_spat[(blk*SP_ + sp)*CG_ + cg] = sacc * (1.f / T_);
    }
    g_temp[(blk*T_ + 2*tg    )*CG_ + cg] = tacc0 * (1.f / SP_);
    g_temp[(blk*T_ + 2*tg + 1)*CG_ + cg] = tacc1 * (1.f / SP_);
}

// ------------------ adaptive mixing (spatial) -----------------------------
__global__ void __launch_bounds__(256)
k_mix_s() {
    __shared__ float xs[2048];
    __shared__ float ms[4096];
    __shared__ float o1[2048];
    __shared__ float red[16];
    int blk = blockIdx.x, g = blk & 3, bq = blk >> 2;
    const float* P = g_ps + (size_t)bq*NS_ + g*PS_;
    const float* X = g_spat + (size_t)blk*2048;
    int tid = threadIdx.x;
    for (int i = tid; i < 2048; i += 256) xs[i] = X[i];
    for (int i = tid; i < 4096; i += 256) ms[i] = P[i];
    __syncthreads();
    // out1[p][d] = sum_c x[p][c]*M[c][d]   (32x64)
    int p = tid >> 3, d0 = (tid & 7) * 8;
    float acc[8] = {};
    for (int c = 0; c < 64; c++) {
        float xv = xs[p*64 + c];
        #pragma unroll
        for (int j = 0; j < 8; j++) acc[j] += xv * ms[c*64 + d0 + j];
    }
    float s = 0.f, q = 0.f;
    #pragma unroll
    for (int j = 0; j < 8; j++) { s += acc[j]; q += acc[j]*acc[j]; }
    blockReduce2(s, q, red);
    float mu = s * (1.f/2048.f);
    float var = fmaxf(q * (1.f/2048.f) - mu*mu, 0.f);
    float rstd = rsqrtf(var + 1e-5f);
    #pragma unroll
    for (int j = 0; j < 8; j++) o1[p*64 + d0 + j] = fmaxf((acc[j]-mu)*rstd, 0.f);
    for (int i = tid; i < 4096; i += 256) ms[i] = P[4096 + i];   // S (128x32)
    __syncthreads();
    // out2[o][d] = sum_p S[o][p]*out1[p][d]  (128x64)
    int o = tid >> 1, e0 = (tid & 1) * 32;
    float a2[32] = {};
    for (int pp = 0; pp < 32; pp++) {
        float sv = ms[o*32 + pp];
        #pragma unroll
        for (int j = 0; j < 32; j++) a2[j] += sv * o1[pp*64 + e0 + j];
    }
    s = 0.f; q = 0.f;
    #pragma unroll
    for (int j = 0; j < 32; j++) { s += a2[j]; q += a2[j]*a2[j]; }
    blockReduce2(s, q, red);
    mu = s * (1.f/8192.f);
    var = fmaxf(q * (1.f/8192.f) - mu*mu, 0.f);
    rstd = rsqrtf(var + 1e-5f);
    float* Co = g_mixs + (size_t)bq*NS_ + g*PS_;
    #pragma unroll
    for (int j = 0; j < 32; j++)
        Co[o*64 + e0 + j] = fmaxf((a2[j]-mu)*rstd, 0.f);
}

// ------------------ adaptive mixing (temporal) ----------------------------
__global__ void __launch_bounds__(256)
k_mix_t() {
    __shared__ float xs[512];
    __shared__ float ms[4096];
    __shared__ float o1[512];
    __shared__ float red[16];
    int blk = blockIdx.x, g = blk & 3, bq = blk >> 2;
    const float* P = g_pt + (size_t)bq*NT_ + g*PT_;
    const float* X = g_temp + (size_t)blk*512;
    int tid = threadIdx.x;
    for (int i = tid; i < 512; i += 256) xs[i] = X[i];
    for (int i = tid; i < 4096; i += 256) ms[i] = P[i];
    __syncthreads();
    // out1[p][d], p in [0,8), d in [0,64)
    int p = tid >> 5, d0 = (tid & 31) * 2;
    float acc[2] = {};
    for (int c = 0; c < 64; c++) {
        float xv = xs[p*64 + c];
        acc[0] += xv * ms[c*64 + d0];
        acc[1] += xv * ms[c*64 + d0 + 1];
    }
    float s = acc[0] + acc[1], q = acc[0]*acc[0] + acc[1]*acc[1];
    blockReduce2(s, q, red);
    float mu = s * (1.f/512.f);
    float var = fmaxf(q * (1.f/512.f) - mu*mu, 0.f);
    float rstd = rsqrtf(var + 1e-5f);
    o1[p*64 + d0]     = fmaxf((acc[0]-mu)*rstd, 0.f);
    o1[p*64 + d0 + 1] = fmaxf((acc[1]-mu)*rstd, 0.f);
    for (int i = tid; i < 256; i += 256) ms[i] = P[4096 + i];   // S (32x8)
    __syncthreads();
    // out2[o][d], o in [0,32), d in [0,64)
    int o = tid >> 3, e0 = (tid & 7) * 8;
    float a2[8] = {};
    #pragma unroll
    for (int pp = 0; pp < 8; pp++) {
        float sv = ms[o*8 + pp];
        #pragma unroll
        for (int j = 0; j < 8; j++) a2[j] += sv * o1[pp*64 + e0 + j];
    }
    s = 0.f; q = 0.f;
    #pragma unroll
    for (int j = 0; j < 8; j++) { s += a2[j]; q += a2[j]*a2[j]; }
    blockReduce2(s, q, red);
    mu = s * (1.f/2048.f);
    var = fmaxf(q * (1.f/2048.f) - mu*mu, 0.f);
    rstd = rsqrtf(var + 1e-5f);
    float* Co = g_mixt + (size_t)bq*(G_*32*CG_) + g*(32*CG_);
    #pragma unroll
    for (int j = 0; j < 8; j++)
        Co[o*64 + e0 + j] = fmaxf((a2[j]-mu)*rstd, 0.f);
}

// ------------------ split-K reduce + bias + residual + LayerNorm ---------
__global__ void __launch_bounds__(256)
k_epilogue(const float* __restrict__ part, int nsplit,
           const float* __restrict__ bias, const float* __restrict__ query,
           const float* __restrict__ gamma, const float* __restrict__ beta,
           float* __restrict__ out) {
    __shared__ float red[16];
    int m = blockIdx.x, d = threadIdx.x;
    float v = bias[d] + query[m*D_ + d];
    for (int s = 0; s < nsplit; s++) v += part[(size_t)(s*BQ_ + m)*D_ + d];
    float s1 = v, q1 = v*v;
    blockReduce2(s1, q1, red);
    float mu = s1 * (1.f/256.f);
    float var = fmaxf(q1 * (1.f/256.f) - mu*mu, 0.f);
    out[m*D_ + d] = (v - mu) * rsqrtf(var + 1e-5f) * gamma[d] + beta[d];
}

// ------------------ launch ------------------------------------------------
static float* sym(const void* s) {
    void* p = nullptr;
    cudaGetSymbolAddress(&p, s);
    return (float*)p;
}

extern "C" void kernel_launch(void* const* d_in, const int* in_sizes, int n_in,
                              void* d_out, int out_size) {
    const float* feat0 = (const float*)d_in[0];
    const float* feat1 = (const float*)d_in[1];
    const float* feat2 = (const float*)d_in[2];
    const float* feat3 = (const float*)d_in[3];
    const float* boxes = (const float*)d_in[4];
    const float* squer = (const float*)d_in[5];
    const float* tquer = (const float*)d_in[6];
    const float* W_off = (const float*)d_in[7];
    const float* b_off = (const float*)d_in[8];
    const float* W_ps  = (const float*)d_in[9];
    const float* b_ps  = (const float*)d_in[10];
    const float* Wo_s  = (const float*)d_in[11];
    const float* bo_s  = (const float*)d_in[12];
    const float* g_s   = (const float*)d_in[13];
    const float* be_s  = (const float*)d_in[14];
    const float* W_pt  = (const float*)d_in[15];
    const float* b_pt  = (const float*)d_in[16];
    const float* Wo_t  = (const float*)d_in[17];
    const float* bo_t  = (const float*)d_in[18];
    const float* g_t   = (const float*)d_in[19];
    const float* be_t  = (const float*)d_in[20];
    float* out = (float*)d_out;

    float* p_ftr0 = sym(g_ftr0); float* p_ftr1 = sym(g_ftr1);
    float* p_ftr2 = sym(g_ftr2); float* p_ftr3 = sym(g_ftr3);
    float* p_off  = sym(g_off);
    float* p_ps   = sym(g_ps);   float* p_pt   = sym(g_pt);
    float* p_mixs = sym(g_mixs); float* p_mixt = sym(g_mixt);
    float* p_parts = sym(g_part_s); float* p_partt = sym(g_part_t);

    // 1) feature transpose to (b,y,x,c,t)
    k_transpose<<<dim3(2, 8, B_*64), 256>>>(feat0, p_ftr0, 64, 64);
    k_transpose<<<dim3(1, 8, B_*32), 256>>>(feat1, p_ftr1, 32, 32);
    k_transpose<<<dim3(1, 8, B_*16), 256>>>(feat2, p_ftr2, 16, 16);
    k_transpose<<<dim3(1, 8, B_*8 ), 256>>>(feat3, p_ftr3, 8, 8);

    // 2) projections  (M-tiles of 128: ceil(400/128)=4)
    k_gemm<<<dim3(384/64,   4, 1), 256>>>(squer, W_off, b_off, p_off, BQ_, 384, D_, D_);
    k_gemm<<<dim3(NS_/64,   4, 1), 256>>>(squer, W_ps,  b_ps,  p_ps,  BQ_, NS_, D_, D_);
    k_gemm<<<dim3(NT_/64,   4, 1), 256>>>(tquer, W_pt,  b_pt,  p_pt,  BQ_, NT_, D_, D_);

    // 3) sampling (fused T-mean and SP-mean)
    k_sample<<<BQ_*G_, 256>>>(boxes);

    // 4) adaptive mixing
    k_mix_s<<<BQ_*G_, 256>>>();
    k_mix_t<<<BQ_*G_, 256>>>();

    // 5) output GEMMs (deterministic split-K)
    k_gemm<<<dim3(D_/64, 4, NSPLIT_S), 256>>>(p_mixs, Wo_s, nullptr, p_parts, BQ_, D_, NS_,       NS_/NSPLIT_S);
    k_gemm<<<dim3(D_/64, 4, NSPLIT_T), 256>>>(p_mixt, Wo_t, nullptr, p_partt, BQ_, D_, G_*32*CG_, (G_*32*CG_)/NSPLIT_T);

    // 6) reduce + residual + LN
    k_epilogue<<<BQ_, 256>>>(p_parts, NSPLIT_S, bo_s, squer, g_s, be_s, out);
    k_epilogue<<<BQ_, 256>>>(p_partt, NSPLIT_T, bo_t, tquer, g_t, be_t, out + BQ_*D_);
}

// round 6
// speedup vs baseline: 1.0577x; 1.0577x over previous
#include <cuda_runtime.h>
#include <math.h>
#include <stdint.h>

#define B_    4
#define Q_    100
#define T_    8
#define G_    4
#define CG_   64
#define SP_   32
#define D_    256
#define BQ_   (B_*Q_)         // 400
#define PS_   8192
#define PT_   4352
#define NS_   (G_*PS_)        // 32768
#define NT_   (G_*PT_)        // 17408
#define CT_   (D_*T_)         // 2048

#define NSPLIT_S 32
#define NSPLIT_T 8

// ------------------ scratch (__device__ globals; no allocation allowed) ---
__device__ __align__(16) float g_ftr0[B_*64*64*CT_];
__device__ __align__(16) float g_ftr1[B_*32*32*CT_];
__device__ __align__(16) float g_ftr2[B_*16*16*CT_];
__device__ __align__(16) float g_ftr3[B_*8*8*CT_];
__device__ __align__(16) float g_off[BQ_*384];
__device__ __align__(16) float g_ps [BQ_*NS_];
__device__ __align__(16) float g_pt [BQ_*NT_];
__device__ __align__(16) float g_spat[BQ_*G_*SP_*CG_];
__device__ __align__(16) float g_temp[BQ_*G_*T_*CG_];
__device__ __align__(16) float g_mixs[BQ_*NS_];
__device__ __align__(16) float g_mixt[BQ_*G_*32*CG_];
__device__ __align__(16) float g_part_s[NSPLIT_S*BQ_*D_];
__device__ __align__(16) float g_part_t[NSPLIT_T*BQ_*D_];

// ------------------ packed f32x2 helpers (sm_103a FFMA2 path) -------------
__device__ __forceinline__ uint64_t pack2(float x) {
    uint64_t r;
    asm("mov.b64 %0, {%1, %1};" : "=l"(r) : "f"(x));
    return r;
}
__device__ __forceinline__ void ffma2(uint64_t& d, uint64_t a, uint64_t b) {
    asm("fma.rn.f32x2 %0, %1, %2, %0;" : "+l"(d) : "l"(a), "l"(b));
}
__device__ __forceinline__ void unpack2(uint64_t v, float& lo, float& hi) {
    asm("mov.b64 {%0, %1}, %2;" : "=f"(lo), "=f"(hi) : "l"(v));
}

// ------------------ block reduce (sum, sumsq), blockDim = 256 -------------
__device__ __forceinline__ void blockReduce2(float& s, float& q, float* red) {
    #pragma unroll
    for (int o = 16; o; o >>= 1) {
        s += __shfl_xor_sync(0xffffffffu, s, o);
        q += __shfl_xor_sync(0xffffffffu, q, o);
    }
    int w = threadIdx.x >> 5, lane = threadIdx.x & 31;
    if (lane == 0) { red[w] = s; red[8 + w] = q; }
    __syncthreads();
    if (w == 0) {
        s = red[lane & 7]; q = red[8 + (lane & 7)];
        #pragma unroll
        for (int o = 4; o; o >>= 1) {
            s += __shfl_xor_sync(0xffffffffu, s, o);
            q += __shfl_xor_sync(0xffffffffu, q, o);
        }
        if (lane == 0) { red[0] = s; red[1] = q; }
    }
    __syncthreads();
    s = red[0]; q = red[1];
    __syncthreads();
}

// ------------------ feature transpose: (b,c,t,y,x) -> (b,y,x,c,t) ---------
__global__ void k_transpose(const float* __restrict__ src, float* __restrict__ dst,
                            int H, int W) {
    __shared__ float tile[256][33];
    int tid = threadIdx.x;
    int xb = blockIdx.x * 32;
    int cb = blockIdx.y * 32;
    int b  = blockIdx.z / H, y = blockIdx.z % H;
    int x  = tid & 31;
    int sub = tid >> 5;
    if (xb + x < W) {
        #pragma unroll
        for (int i = 0; i < 32; i++) {
            int ct = i * 8 + sub;
            int c = cb + (ct >> 3), t = ct & 7;
            tile[ct][x] = src[(((b*D_ + c)*T_ + t)*H + y)*W + xb + x];
        }
    }
    __syncthreads();
    int xmax = W - xb; if (xmax > 32) xmax = 32;
    for (int xx = 0; xx < xmax; xx++) {
        dst[((b*H + y)*W + xb + xx)*CT_ + cb*8 + tid] = tile[tid][xx];
    }
}

// ------------------ tiled GEMM 128x64xBK32, 8x4/thread, FFMA2, split-K ----
// C[split] (M x N) = A(M x K-slice) * W(K x N) [+ bias]
// Requires: N % 64 == 0, kc % 32 == 0, K % 4 == 0 (all call sites satisfy).
__global__ void __launch_bounds__(256)
k_gemm(const float* __restrict__ A, const float* __restrict__ Wm,
       const float* __restrict__ bias, float* __restrict__ Cbase,
       int M, int N, int K, int kc) {
    // Stride 132 (multiple of 4): every &As[k][8*ty] is 16B aligned.
    __shared__ float As[32][132];   // [k][m]
    __shared__ float Bs[32][64];    // [k][n]
    int split = blockIdx.z;
    int k0 = split * kc;
    float* C = Cbase + (size_t)split * M * N;
    int tid = threadIdx.x;
    int m0 = blockIdx.y * 128, n0 = blockIdx.x * 64;
    int tx = tid & 15, ty = tid >> 4;           // 16 x 16 thread grid
    int arow = tid >> 3, akq = tid & 7;         // A: float4 per (row, kq)
    int bk = tid >> 4, bnq = tid & 15;          // B: float4 per (k, nq)
    // acc2[p][j] = packed (acc[2p][j], acc[2p+1][j])
    uint64_t acc2[4][4] = {};
    for (int kk = k0; kk < k0 + kc; kk += 32) {
        #pragma unroll
        for (int r = 0; r < 4; r++) {
            int row = arow + r * 32;            // 0..127
            int m = m0 + row;
            float4 v = make_float4(0.f, 0.f, 0.f, 0.f);
            if (m < M) v = *(const float4*)(A + (size_t)m*K + kk + akq*4);
            As[akq*4 + 0][row] = v.x;
            As[akq*4 + 1][row] = v.y;
            As[akq*4 + 2][row] = v.z;
            As[akq*4 + 3][row] = v.w;
        }
        #pragma unroll
        for (int r = 0; r < 2; r++) {
            int k = bk + r * 16;                // 0..31
            *(float4*)(&Bs[k][bnq*4]) =
                *(const float4*)(Wm + (size_t)(kk + k)*N + n0 + bnq*4);
        }
        __syncthreads();
        #pragma unroll
        for (int k = 0; k < 32; k++) {
            // A fragment: 8 consecutive floats = 4 packed f32x2 (16B aligned)
            ulonglong2 A0 = *(const ulonglong2*)(&As[k][ty*8]);
            ulonglong2 A1 = *(const ulonglong2*)(&As[k][ty*8 + 4]);
            uint64_t ap[4] = {A0.x, A0.y, A1.x, A1.y};
            float4 b0 = *(const float4*)(&Bs[k][tx*4]);
            uint64_t bd[4] = {pack2(b0.x), pack2(b0.y), pack2(b0.z), pack2(b0.w)};
            #pragma unroll
            for (int p = 0; p < 4; p++)
                #pragma unroll
                for (int j = 0; j < 4; j++)
                    ffma2(acc2[p][j], ap[p], bd[j]);
        }
        __syncthreads();
    }
    #pragma unroll
    for (int p = 0; p < 4; p++) {
        float lo[4], hi[4];
        #pragma unroll
        for (int j = 0; j < 4; j++) unpack2(acc2[p][j], lo[j], hi[j]);
        int n = n0 + tx*4;
        float bx = 0.f, by = 0.f, bz = 0.f, bw = 0.f;
        if (bias) { bx = bias[n]; by = bias[n+1]; bz = bias[n+2]; bw = bias[n+3]; }
        int mlo = m0 + ty*8 + 2*p;
        if (mlo < M) {
            float4 o; o.x = lo[0]+bx; o.y = lo[1]+by; o.z = lo[2]+bz; o.w = lo[3]+bw;
            *(float4*)(C + (size_t)mlo*N + n) = o;
        }
        int mhi = mlo + 1;
        if (mhi < M) {
            float4 o; o.x = hi[0]+bx; o.y = hi[1]+by; o.z = hi[2]+bz; o.w = hi[3]+bw;
            *(float4*)(C + (size_t)mhi*N + n) = o;
        }
    }
}

// ------------------ bilinear sampling + T-mean / SP-mean fusion ----------
__global__ void __launch_bounds__(256)
k_sample(const float* __restrict__ boxes) {
    __shared__ float spx[SP_][4], spy[SP_][4], slw[SP_][4];
    int blk = blockIdx.x;            // bq*4 + g
    int g  = blk & 3;
    int bq = blk >> 2;
    int b  = bq / Q_;
    int tid = threadIdx.x;
    const float* pb = boxes + bq * 4;
    float cx = pb[0], cy = pb[1], zb = pb[2], rb = pb[3];
    if (tid < 128) {
        int sp = tid >> 2, l = tid & 3;
        const float* po = g_off + bq*384 + (g*SP_ + sp)*3;
        float X = cx + po[0] * exp2f(zb - 0.5f*rb);
        float Y = cy + po[1] * exp2f(zb + 0.5f*rb);
        float mapped = zb + po[2] - 2.0f;     // z - log2(4)
        float dl = mapped - (float)l;
        float e = __expf(-0.5f * dl * dl);
        float s = e;
        s += __shfl_xor_sync(0xffffffffu, s, 1);
        s += __shfl_xor_sync(0xffffffffu, s, 2);
        float inv_stride = 1.0f / (float)(4 << l);
        spx[sp][l] = X * inv_stride - 0.5f;
        spy[sp][l] = Y * inv_stride - 0.5f;
        slw[sp][l] = e / s;
    }
    __syncthreads();

    int cg = tid >> 2, tg = tid & 3;          // thread owns t = 2*tg, 2*tg+1
    int coff = g*(CG_*T_) + cg*T_ + 2*tg;
    float tacc0 = 0.f, tacc1 = 0.f;
    for (int sp = 0; sp < SP_; sp++) {
        float sacc = 0.f;
        #pragma unroll
        for (int l = 0; l < 4; l++) {
            const float* F; int H;
            if      (l == 0) { F = g_ftr0; H = 64; }
            else if (l == 1) { F = g_ftr1; H = 32; }
            else if (l == 2) { F = g_ftr2; H = 16; }
            else             { F = g_ftr3; H = 8;  }
            float w  = slw[sp][l];
            float px = spx[sp][l], py = spy[sp][l];
            float x0f = floorf(px), y0f = floorf(py);
            float fx = px - x0f, fy = py - y0f;
            int x0 = (int)x0f, y0 = (int)y0f;
            #pragma unroll
            for (int tap = 0; tap < 4; tap++) {
                int dx = tap & 1, dy = tap >> 1;
                int xi = x0 + dx, yi = y0 + dy;
                if (xi < 0 || xi >= H || yi < 0 || yi >= H) continue;
                float wt = w * (dx ? fx : 1.f - fx) * (dy ? fy : 1.f - fy);
                const float2* p = (const float2*)(F + ((b*H + yi)*H + xi)*CT_ + coff);
                float2 v = *p;
                tacc0 += wt * v.x;
                tacc1 += wt * v.y;
                sacc  += wt * (v.x + v.y);
            }
        }
        sacc += __shfl_xor_sync(0xffffffffu, sacc, 1);
        sacc += __shfl_xor_sync(0xffffffffu, sacc, 2);
        if (tg == 0) g_spat[(blk*SP_ + sp)*CG_ + cg] = sacc * (1.f / T_);
    }
    g_temp[(blk*T_ + 2*tg    )*CG_ + cg] = tacc0 * (1.f / SP_);
    g_temp[(blk*T_ + 2*tg + 1)*CG_ + cg] = tacc1 * (1.f / SP_);
}

// ------------------ adaptive mixing (spatial) -----------------------------
__global__ void __launch_bounds__(256)
k_mix_s() {
    __shared__ float xs[2048];
    __shared__ float ms[4096];
    __shared__ float o1[2048];
    __shared__ float red[16];
    int blk = blockIdx.x, g = blk & 3, bq = blk >> 2;
    const float* P = g_ps + (size_t)bq*NS_ + g*PS_;
    const float* X = g_spat + (size_t)blk*2048;
    int tid = threadIdx.x;
    for (int i = tid; i < 2048; i += 256) xs[i] = X[i];
    for (int i = tid; i < 4096; i += 256) ms[i] = P[i];
    __syncthreads();
    // out1[p][d] = sum_c x[p][c]*M[c][d]   (32x64)
    int p = tid >> 3, d0 = (tid & 7) * 8;
    float acc[8] = {};
    for (int c = 0; c < 64; c++) {
        float xv = xs[p*64 + c];
        #pragma unroll
        for (int j = 0; j < 8; j++) acc[j] += xv * ms[c*64 + d0 + j];
    }
    float s = 0.f, q = 0.f;
    #pragma unroll
    for (int j = 0; j < 8; j++) { s += acc[j]; q += acc[j]*acc[j]; }
    blockReduce2(s, q, red);
    float mu = s * (1.f/2048.f);
    float var = fmaxf(q * (1.f/2048.f) - mu*mu, 0.f);
    float rstd = rsqrtf(var + 1e-5f);
    #pragma unroll
    for (int j = 0; j < 8; j++) o1[p*64 + d0 + j] = fmaxf((acc[j]-mu)*rstd, 0.f);
    for (int i = tid; i < 4096; i += 256) ms[i] = P[4096 + i];   // S (128x32)
    __syncthreads();
    // out2[o][d] = sum_p S[o][p]*out1[p][d]  (128x64)
    int o = tid >> 1, e0 = (tid & 1) * 32;
    float a2[32] = {};
    for (int pp = 0; pp < 32; pp++) {
        float sv = ms[o*32 + pp];
        #pragma unroll
        for (int j = 0; j < 32; j++) a2[j] += sv * o1[pp*64 + e0 + j];
    }
    s = 0.f; q = 0.f;
    #pragma unroll
    for (int j = 0; j < 32; j++) { s += a2[j]; q += a2[j]*a2[j]; }
    blockReduce2(s, q, red);
    mu = s * (1.f/8192.f);
    var = fmaxf(q * (1.f/8192.f) - mu*mu, 0.f);
    rstd = rsqrtf(var + 1e-5f);
    float* Co = g_mixs + (size_t)bq*NS_ + g*PS_;
    #pragma unroll
    for (int j = 0; j < 32; j++)
        Co[o*64 + e0 + j] = fmaxf((a2[j]-mu)*rstd, 0.f);
}

// ------------------ adaptive mixing (temporal) ----------------------------
__global__ void __launch_bounds__(256)
k_mix_t() {
    __shared__ float xs[512];
    __shared__ float ms[4096];
    __shared__ float o1[512];
    __shared__ float red[16];
    int blk = blockIdx.x, g = blk & 3, bq = blk >> 2;
    const float* P = g_pt + (size_t)bq*NT_ + g*PT_;
    const float* X = g_temp + (size_t)blk*512;
    int tid = threadIdx.x;
    for (int i = tid; i < 512; i += 256) xs[i] = X[i];
    for (int i = tid; i < 4096; i += 256) ms[i] = P[i];
    __syncthreads();
    // out1[p][d], p in [0,8), d in [0,64)
    int p = tid >> 5, d0 = (tid & 31) * 2;
    float acc[2] = {};
    for (int c = 0; c < 64; c++) {
        float xv = xs[p*64 + c];
        acc[0] += xv * ms[c*64 + d0];
        acc[1] += xv * ms[c*64 + d0 + 1];
    }
    float s = acc[0] + acc[1], q = acc[0]*acc[0] + acc[1]*acc[1];
    blockReduce2(s, q, red);
    float mu = s * (1.f/512.f);
    float var = fmaxf(q * (1.f/512.f) - mu*mu, 0.f);
    float rstd = rsqrtf(var + 1e-5f);
    o1[p*64 + d0]     = fmaxf((acc[0]-mu)*rstd, 0.f);
    o1[p*64 + d0 + 1] = fmaxf((acc[1]-mu)*rstd, 0.f);
    for (int i = tid; i < 256; i += 256) ms[i] = P[4096 + i];   // S (32x8)
    __syncthreads();
    // out2[o][d], o in [0,32), d in [0,64)
    int o = tid >> 3, e0 = (tid & 7) * 8;
    float a2[8] = {};
    #pragma unroll
    for (int pp = 0; pp < 8; pp++) {
        float sv = ms[o*8 + pp];
        #pragma unroll
        for (int j = 0; j < 8; j++) a2[j] += sv * o1[pp*64 + e0 + j];
    }
    s = 0.f; q = 0.f;
    #pragma unroll
    for (int j = 0; j < 8; j++) { s += a2[j]; q += a2[j]*a2[j]; }
    blockReduce2(s, q, red);
    mu = s * (1.f/2048.f);
    var = fmaxf(q * (1.f/2048.f) - mu*mu, 0.f);
    rstd = rsqrtf(var + 1e-5f);
    float* Co = g_mixt + (size_t)bq*(G_*32*CG_) + g*(32*CG_);
    #pragma unroll
    for (int j = 0; j < 8; j++)
        Co[o*64 + e0 + j] = fmaxf((a2[j]-mu)*rstd, 0.f);
}

// ------------------ split-K reduce + bias + residual + LayerNorm ---------
__global__ void __launch_bounds__(256)
k_epilogue(const float* __restrict__ part, int nsplit,
           const float* __restrict__ bias, const float* __restrict__ query,
           const float* __restrict__ gamma, const float* __restrict__ beta,
           float* __restrict__ out) {
    __shared__ float red[16];
    int m = blockIdx.x, d = threadIdx.x;
    float v = bias[d] + query[m*D_ + d];
    for (int s = 0; s < nsplit; s++) v += part[(size_t)(s*BQ_ + m)*D_ + d];
    float s1 = v, q1 = v*v;
    blockReduce2(s1, q1, red);
    float mu = s1 * (1.f/256.f);
    float var = fmaxf(q1 * (1.f/256.f) - mu*mu, 0.f);
    out[m*D_ + d] = (v - mu) * rsqrtf(var + 1e-5f) * gamma[d] + beta[d];
}

// ------------------ launch ------------------------------------------------
static float* sym(const void* s) {
    void* p = nullptr;
    cudaGetSymbolAddress(&p, s);
    return (float*)p;
}

extern "C" void kernel_launch(void* const* d_in, const int* in_sizes, int n_in,
                              void* d_out, int out_size) {
    const float* feat0 = (const float*)d_in[0];
    const float* feat1 = (const float*)d_in[1];
    const float* feat2 = (const float*)d_in[2];
    const float* feat3 = (const float*)d_in[3];
    const float* boxes = (const float*)d_in[4];
    const float* squer = (const float*)d_in[5];
    const float* tquer = (const float*)d_in[6];
    const float* W_off = (const float*)d_in[7];
    const float* b_off = (const float*)d_in[8];
    const float* W_ps  = (const float*)d_in[9];
    const float* b_ps  = (const float*)d_in[10];
    const float* Wo_s  = (const float*)d_in[11];
    const float* bo_s  = (const float*)d_in[12];
    const float* g_s   = (const float*)d_in[13];
    const float* be_s  = (const float*)d_in[14];
    const float* W_pt  = (const float*)d_in[15];
    const float* b_pt  = (const float*)d_in[16];
    const float* Wo_t  = (const float*)d_in[17];
    const float* bo_t  = (const float*)d_in[18];
    const float* g_t   = (const float*)d_in[19];
    const float* be_t  = (const float*)d_in[20];
    float* out = (float*)d_out;

    float* p_ftr0 = sym(g_ftr0); float* p_ftr1 = sym(g_ftr1);
    float* p_ftr2 = sym(g_ftr2); float* p_ftr3 = sym(g_ftr3);
    float* p_off  = sym(g_off);
    float* p_ps   = sym(g_ps);   float* p_pt   = sym(g_pt);
    float* p_mixs = sym(g_mixs); float* p_mixt = sym(g_mixt);
    float* p_parts = sym(g_part_s); float* p_partt = sym(g_part_t);

    // 1) feature transpose to (b,y,x,c,t)
    k_transpose<<<dim3(2, 8, B_*64), 256>>>(feat0, p_ftr0, 64, 64);
    k_transpose<<<dim3(1, 8, B_*32), 256>>>(feat1, p_ftr1, 32, 32);
    k_transpose<<<dim3(1, 8, B_*16), 256>>>(feat2, p_ftr2, 16, 16);
    k_transpose<<<dim3(1, 8, B_*8 ), 256>>>(feat3, p_ftr3, 8, 8);

    // 2) projections  (M-tiles of 128: ceil(400/128)=4)
    k_gemm<<<dim3(384/64,   4, 1), 256>>>(squer, W_off, b_off, p_off, BQ_, 384, D_, D_);
    k_gemm<<<dim3(NS_/64,   4, 1), 256>>>(squer, W_ps,  b_ps,  p_ps,  BQ_, NS_, D_, D_);
    k_gemm<<<dim3(NT_/64,   4, 1), 256>>>(tquer, W_pt,  b_pt,  p_pt,  BQ_, NT_, D_, D_);

    // 3) sampling (fused T-mean and SP-mean)
    k_sample<<<BQ_*G_, 256>>>(boxes);

    // 4) adaptive mixing
    k_mix_s<<<BQ_*G_, 256>>>();
    k_mix_t<<<BQ_*G_, 256>>>();

    // 5) output GEMMs (deterministic split-K)
    k_gemm<<<dim3(D_/64, 4, NSPLIT_S), 256>>>(p_mixs, Wo_s, nullptr, p_parts, BQ_, D_, NS_,       NS_/NSPLIT_S);
    k_gemm<<<dim3(D_/64, 4, NSPLIT_T), 256>>>(p_mixt, Wo_t, nullptr, p_partt, BQ_, D_, G_*32*CG_, (G_*32*CG_)/NSPLIT_T);

    // 6) reduce + residual + LN
    k_epilogue<<<BQ_, 256>>>(p_parts, NSPLIT_S, bo_s, squer, g_s, be_s, out);
    k_epilogue<<<BQ_, 256>>>(p_partt, NSPLIT_T, bo_t, tquer, g_t, be_t, out + BQ_*D_);
}

// round 16
// speedup vs baseline: 1.1046x; 1.0444x over previous
#include <cuda_runtime.h>
#include <math.h>
#include <stdint.h>

#define B_    4
#define Q_    100
#define T_    8
#define G_    4
#define CG_   64
#define SP_   32
#define D_    256
#define BQ_   (B_*Q_)         // 400
#define PS_   8192
#define PT_   4352
#define NS_   (G_*PS_)        // 32768
#define NT_   (G_*PT_)        // 17408
#define CT_   (D_*T_)         // 2048

#define NSPLIT_S 32
#define NSPLIT_T 8

// ------------------ scratch (__device__ globals; no allocation allowed) ---
__device__ __align__(16) float g_ftr0[B_*64*64*CT_];
__device__ __align__(16) float g_ftr1[B_*32*32*CT_];
__device__ __align__(16) float g_ftr2[B_*16*16*CT_];
__device__ __align__(16) float g_ftr3[B_*8*8*CT_];
__device__ __align__(16) float g_off[BQ_*384];
__device__ __align__(16) float g_ps [BQ_*NS_];
__device__ __align__(16) float g_pt [BQ_*NT_];
__device__ __align__(16) float g_spat[BQ_*G_*SP_*CG_];
__device__ __align__(16) float g_temp[BQ_*G_*T_*CG_];
__device__ __align__(16) float g_mixs[BQ_*NS_];
__device__ __align__(16) float g_mixt[BQ_*G_*32*CG_];
__device__ __align__(16) float g_part_s[NSPLIT_S*BQ_*D_];
__device__ __align__(16) float g_part_t[NSPLIT_T*BQ_*D_];

// ------------------ packed f32x2 helpers (sm_103a FFMA2 path) -------------
__device__ __forceinline__ uint64_t pack2(float x) {
    uint64_t r;
    asm("mov.b64 %0, {%1, %1};" : "=l"(r) : "f"(x));
    return r;
}
__device__ __forceinline__ void ffma2(uint64_t& d, uint64_t a, uint64_t b) {
    asm("fma.rn.f32x2 %0, %1, %2, %0;" : "+l"(d) : "l"(a), "l"(b));
}
__device__ __forceinline__ void unpack2(uint64_t v, float& lo, float& hi) {
    asm("mov.b64 {%0, %1}, %2;" : "=f"(lo), "=f"(hi) : "l"(v));
}

// ------------------ block reduce (sum, sumsq), blockDim = 256 -------------
__device__ __forceinline__ void blockReduce2(float& s, float& q, float* red) {
    #pragma unroll
    for (int o = 16; o; o >>= 1) {
        s += __shfl_xor_sync(0xffffffffu, s, o);
        q += __shfl_xor_sync(0xffffffffu, q, o);
    }
    int w = threadIdx.x >> 5, lane = threadIdx.x & 31;
    if (lane == 0) { red[w] = s; red[8 + w] = q; }
    __syncthreads();
    if (w == 0) {
        s = red[lane & 7]; q = red[8 + (lane & 7)];
        #pragma unroll
        for (int o = 4; o; o >>= 1) {
            s += __shfl_xor_sync(0xffffffffu, s, o);
            q += __shfl_xor_sync(0xffffffffu, q, o);
        }
        if (lane == 0) { red[0] = s; red[1] = q; }
    }
    __syncthreads();
    s = red[0]; q = red[1];
    __syncthreads();
}

// ------------------ feature transpose: (b,c,t,y,x) -> (b,y,x,c,t) ---------
__global__ void k_transpose(const float* __restrict__ src, float* __restrict__ dst,
                            int H, int W) {
    __shared__ float tile[256][33];
    int tid = threadIdx.x;
    int xb = blockIdx.x * 32;
    int cb = blockIdx.y * 32;
    int b  = blockIdx.z / H, y = blockIdx.z % H;
    int x  = tid & 31;
    int sub = tid >> 5;
    if (xb + x < W) {
        #pragma unroll
        for (int i = 0; i < 32; i++) {
            int ct = i * 8 + sub;
            int c = cb + (ct >> 3), t = ct & 7;
            tile[ct][x] = src[(((b*D_ + c)*T_ + t)*H + y)*W + xb + x];
        }
    }
    __syncthreads();
    int xmax = W - xb; if (xmax > 32) xmax = 32;
    for (int xx = 0; xx < xmax; xx++) {
        dst[((b*H + y)*W + xb + xx)*CT_ + cb*8 + tid] = tile[tid][xx];
    }
}

// ------------------ tiled GEMM 128x64xBK32, FFMA2, reg double-buffer ------
// C[split] (M x N) = A(M x K-slice) * W(K x N) [+ bias]
// Requires: N % 64 == 0, kc % 32 == 0, K % 4 == 0 (all call sites satisfy).
__global__ void __launch_bounds__(256)
k_gemm(const float* __restrict__ A, const float* __restrict__ Wm,
       const float* __restrict__ bias, float* __restrict__ Cbase,
       int M, int N, int K, int kc) {
    // Stride 132 (multiple of 4): every &As[k][8*ty] is 16B aligned.
    __shared__ float As[32][132];   // [k][m]
    __shared__ float Bs[32][64];    // [k][n]
    int split = blockIdx.z;
    int k0 = split * kc;
    float* C = Cbase + (size_t)split * M * N;
    int tid = threadIdx.x;
    int m0 = blockIdx.y * 128, n0 = blockIdx.x * 64;
    int tx = tid & 15, ty = tid >> 4;           // 16 x 16 thread grid
    int arow = tid >> 3, akq = tid & 7;         // A: float4 per (row, kq)
    int bk = tid >> 4, bnq = tid & 15;          // B: float4 per (k, nq)
    uint64_t acc2[4][4] = {};
    float4 aR[4], bR[2];
    // prefetch tile 0 into registers
    #pragma unroll
    for (int r = 0; r < 4; r++) {
        int m = m0 + arow + r * 32;
        aR[r] = (m < M) ? *(const float4*)(A + (size_t)m*K + k0 + akq*4)
                        : make_float4(0.f, 0.f, 0.f, 0.f);
    }
    #pragma unroll
    for (int r = 0; r < 2; r++) {
        int k = bk + r * 16;
        bR[r] = *(const float4*)(Wm + (size_t)(k0 + k)*N + n0 + bnq*4);
    }
    int niter = kc >> 5;
    for (int it = 0; it < niter; it++) {
        // commit prefetched regs to smem
        #pragma unroll
        for (int r = 0; r < 4; r++) {
            int row = arow + r * 32;
            As[akq*4 + 0][row] = aR[r].x;
            As[akq*4 + 1][row] = aR[r].y;
            As[akq*4 + 2][row] = aR[r].z;
            As[akq*4 + 3][row] = aR[r].w;
        }
        #pragma unroll
        for (int r = 0; r < 2; r++) {
            int k = bk + r * 16;
            *(float4*)(&Bs[k][bnq*4]) = bR[r];
        }
        __syncthreads();
        // issue next tile's global loads (land during compute)
        if (it + 1 < niter) {
            int kk = k0 + (it + 1) * 32;
            #pragma unroll
            for (int r = 0; r < 4; r++) {
                int m = m0 + arow + r * 32;
                aR[r] = (m < M) ? *(const float4*)(A + (size_t)m*K + kk + akq*4)
                                : make_float4(0.f, 0.f, 0.f, 0.f);
            }
            #pragma unroll
            for (int r = 0; r < 2; r++) {
                int k = bk + r * 16;
                bR[r] = *(const float4*)(Wm + (size_t)(kk + k)*N + n0 + bnq*4);
            }
        }
        #pragma unroll
        for (int k = 0; k < 32; k++) {
            ulonglong2 A0 = *(const ulonglong2*)(&As[k][ty*8]);
            ulonglong2 A1 = *(const ulonglong2*)(&As[k][ty*8 + 4]);
            uint64_t ap[4] = {A0.x, A0.y, A1.x, A1.y};
            float4 b0 = *(const float4*)(&Bs[k][tx*4]);
            uint64_t bd[4] = {pack2(b0.x), pack2(b0.y), pack2(b0.z), pack2(b0.w)};
            #pragma unroll
            for (int p = 0; p < 4; p++)
                #pragma unroll
                for (int j = 0; j < 4; j++)
                    ffma2(acc2[p][j], ap[p], bd[j]);
        }
        __syncthreads();
    }
    #pragma unroll
    for (int p = 0; p < 4; p++) {
        float lo[4], hi[4];
        #pragma unroll
        for (int j = 0; j < 4; j++) unpack2(acc2[p][j], lo[j], hi[j]);
        int n = n0 + tx*4;
        float bx = 0.f, by = 0.f, bz = 0.f, bw = 0.f;
        if (bias) { bx = bias[n]; by = bias[n+1]; bz = bias[n+2]; bw = bias[n+3]; }
        int mlo = m0 + ty*8 + 2*p;
        if (mlo < M) {
            float4 o; o.x = lo[0]+bx; o.y = lo[1]+by; o.z = lo[2]+bz; o.w = lo[3]+bw;
            *(float4*)(C + (size_t)mlo*N + n) = o;
        }
        int mhi = mlo + 1;
        if (mhi < M) {
            float4 o; o.x = hi[0]+bx; o.y = hi[1]+by; o.z = hi[2]+bz; o.w = hi[3]+bw;
            *(float4*)(C + (size_t)mhi*N + n) = o;
        }
    }
}

// ------------------ bilinear sampling + T-mean / SP-mean fusion ----------
// Thread (half, cg, tg): half = sp parity, cg channel, tg -> t = 4*tg..4*tg+3.
// One float4 LDG per tap (was 2x float2).
__global__ void __launch_bounds__(256)
k_sample(const float* __restrict__ boxes) {
    __shared__ float spx[SP_][4], spy[SP_][4], slw[SP_][4];
    __shared__ float tpart[256*4];
    int blk = blockIdx.x;            // bq*4 + g
    int g  = blk & 3;
    int bq = blk >> 2;
    int b  = bq / Q_;
    int tid = threadIdx.x;
    const float* pb = boxes + bq * 4;
    float cx = pb[0], cy = pb[1], zb = pb[2], rb = pb[3];
    if (tid < 128) {
        int sp = tid >> 2, l = tid & 3;
        const float* po = g_off + bq*384 + (g*SP_ + sp)*3;
        float X = cx + po[0] * exp2f(zb - 0.5f*rb);
        float Y = cy + po[1] * exp2f(zb + 0.5f*rb);
        float mapped = zb + po[2] - 2.0f;     // z - log2(4)
        float dl = mapped - (float)l;
        float e = __expf(-0.5f * dl * dl);
        float s = e;
        s += __shfl_xor_sync(0xffffffffu, s, 1);
        s += __shfl_xor_sync(0xffffffffu, s, 2);
        float inv_stride = 1.0f / (float)(4 << l);
        spx[sp][l] = X * inv_stride - 0.5f;
        spy[sp][l] = Y * inv_stride - 0.5f;
        slw[sp][l] = e / s;
    }
    __syncthreads();

    int half = tid >> 7;                      // sp parity
    int r    = tid & 127;
    int cg   = r >> 1;                        // 0..63
    int tg   = r & 1;                         // t base = 4*tg
    int coff = g*(CG_*T_) + cg*T_ + tg*4;
    float t0 = 0.f, t1 = 0.f, t2 = 0.f, t3 = 0.f;
    for (int spb = 0; spb < SP_; spb += 2) {
        int sp = spb + half;
        float sacc = 0.f;
        #pragma unroll
        for (int l = 0; l < 4; l++) {
            const float* F; int H;
            if      (l == 0) { F = g_ftr0; H = 64; }
            else if (l == 1) { F = g_ftr1; H = 32; }
            else if (l == 2) { F = g_ftr2; H = 16; }
            else             { F = g_ftr3; H = 8;  }
            float w  = slw[sp][l];
            float px = spx[sp][l], py = spy[sp][l];
            float x0f = floorf(px), y0f = floorf(py);
            float fx = px - x0f, fy = py - y0f;
            int x0 = (int)x0f, y0 = (int)y0f;
            #pragma unroll
            for (int tap = 0; tap < 4; tap++) {
                int dx = tap & 1, dy = tap >> 1;
                int xi = x0 + dx, yi = y0 + dy;
                if (xi < 0 || xi >= H || yi < 0 || yi >= H) continue;
                float wt = w * (dx ? fx : 1.f - fx) * (dy ? fy : 1.f - fy);
                float4 v = *(const float4*)(F + ((size_t)(b*H + yi)*H + xi)*CT_ + coff);
                t0 += wt * v.x; t1 += wt * v.y;
                t2 += wt * v.z; t3 += wt * v.w;
                sacc += wt * ((v.x + v.y) + (v.z + v.w));
            }
        }
        sacc += __shfl_xor_sync(0xffffffffu, sacc, 1);   // combine tg pair -> 8 t's
        if (tg == 0) g_spat[(blk*SP_ + sp)*CG_ + cg] = sacc * (1.f / T_);
    }
    // temporal: combine the two sp-halves via smem
    *(float4*)&tpart[tid*4] = make_float4(t0, t1, t2, t3);
    __syncthreads();
    if (half == 0) {
        float4 o = *(const float4*)&tpart[(tid + 128)*4];
        t0 += o.x; t1 += o.y; t2 += o.z; t3 += o.w;
        int tb = tg*4;
        g_temp[(blk*T_ + tb + 0)*CG_ + cg] = t0 * (1.f / SP_);
        g_temp[(blk*T_ + tb + 1)*CG_ + cg] = t1 * (1.f / SP_);
        g_temp[(blk*T_ + tb + 2)*CG_ + cg] = t2 * (1.f / SP_);
        g_temp[(blk*T_ + tb + 3)*CG_ + cg] = t3 * (1.f / SP_);
    }
}

// ------------------ adaptive mixing (spatial) -----------------------------
__global__ void __launch_bounds__(256)
k_mix_s() {
    __shared__ float xs[2048];
    __shared__ float ms[4096];
    __shared__ float o1[2048];
    __shared__ float red[16];
    int blk = blockIdx.x, g = blk & 3, bq = blk >> 2;
    const float* P = g_ps + (size_t)bq*NS_ + g*PS_;
    const float* X = g_spat + (size_t)blk*2048;
    int tid = threadIdx.x;
    for (int i = tid; i < 2048; i += 256) xs[i] = X[i];
    for (int i = tid; i < 4096; i += 256) ms[i] = P[i];
    __syncthreads();
    // out1[p][d] = sum_c x[p][c]*M[c][d]   (32x64)
    int p = tid >> 3, d0 = (tid & 7) * 8;
    float acc[8] = {};
    for (int c = 0; c < 64; c++) {
        float xv = xs[p*64 + c];
        #pragma unroll
        for (int j = 0; j < 8; j++) acc[j] += xv * ms[c*64 + d0 + j];
    }
    float s = 0.f, q = 0.f;
    #pragma unroll
    for (int j = 0; j < 8; j++) { s += acc[j]; q += acc[j]*acc[j]; }
    blockReduce2(s, q, red);
    float mu = s * (1.f/2048.f);
    float var = fmaxf(q * (1.f/2048.f) - mu*mu, 0.f);
    float rstd = rsqrtf(var + 1e-5f);
    #pragma unroll
    for (int j = 0; j < 8; j++) o1[p*64 + d0 + j] = fmaxf((acc[j]-mu)*rstd, 0.f);
    for (int i = tid; i < 4096; i += 256) ms[i] = P[4096 + i];   // S (128x32)
    __syncthreads();
    // out2[o][d] = sum_p S[o][p]*out1[p][d]  (128x64)
    int o = tid >> 1, e0 = (tid & 1) * 32;
    float a2[32] = {};
    for (int pp = 0; pp < 32; pp++) {
        float sv = ms[o*32 + pp];
        #pragma unroll
        for (int j = 0; j < 32; j++) a2[j] += sv * o1[pp*64 + e0 + j];
    }
    s = 0.f; q = 0.f;
    #pragma unroll
    for (int j = 0; j < 32; j++) { s += a2[j]; q += a2[j]*a2[j]; }
    blockReduce2(s, q, red);
    mu = s * (1.f/8192.f);
    var = fmaxf(q * (1.f/8192.f) - mu*mu, 0.f);
    rstd = rsqrtf(var + 1e-5f);
    float* Co = g_mixs + (size_t)bq*NS_ + g*PS_;
    #pragma unroll
    for (int j = 0; j < 32; j++)
        Co[o*64 + e0 + j] = fmaxf((a2[j]-mu)*rstd, 0.f);
}

// ------------------ adaptive mixing (temporal) ----------------------------
__global__ void __launch_bounds__(256)
k_mix_t() {
    __shared__ float xs[512];
    __shared__ float ms[4096];
    __shared__ float o1[512];
    __shared__ float red[16];
    int blk = blockIdx.x, g = blk & 3, bq = blk >> 2;
    const float* P = g_pt + (size_t)bq*NT_ + g*PT_;
    const float* X = g_temp + (size_t)blk*512;
    int tid = threadIdx.x;
    for (int i = tid; i < 512; i += 256) xs[i] = X[i];
    for (int i = tid; i < 4096; i += 256) ms[i] = P[i];
    __syncthreads();
    // out1[p][d], p in [0,8), d in [0,64)
    int p = tid >> 5, d0 = (tid & 31) * 2;
    float acc[2] = {};
    for (int c = 0; c < 64; c++) {
        float xv = xs[p*64 + c];
        acc[0] += xv * ms[c*64 + d0];
        acc[1] += xv * ms[c*64 + d0 + 1];
    }
    float s = acc[0] + acc[1], q = acc[0]*acc[0] + acc[1]*acc[1];
    blockReduce2(s, q, red);
    float mu = s * (1.f/512.f);
    float var = fmaxf(q * (1.f/512.f) - mu*mu, 0.f);
    float rstd = rsqrtf(var + 1e-5f);
    o1[p*64 + d0]     = fmaxf((acc[0]-mu)*rstd, 0.f);
    o1[p*64 + d0 + 1] = fmaxf((acc[1]-mu)*rstd, 0.f);
    for (int i = tid; i < 256; i += 256) ms[i] = P[4096 + i];   // S (32x8)
    __syncthreads();
    // out2[o][d], o in [0,32), d in [0,64)
    int o = tid >> 3, e0 = (tid & 7) * 8;
    float a2[8] = {};
    #pragma unroll
    for (int pp = 0; pp < 8; pp++) {
        float sv = ms[o*8 + pp];
        #pragma unroll
        for (int j = 0; j < 8; j++) a2[j] += sv * o1[pp*64 + e0 + j];
    }
    s = 0.f; q = 0.f;
    #pragma unroll
    for (int j = 0; j < 8; j++) { s += a2[j]; q += a2[j]*a2[j]; }
    blockReduce2(s, q, red);
    mu = s * (1.f/2048.f);
    var = fmaxf(q * (1.f/2048.f) - mu*mu, 0.f);
    rstd = rsqrtf(var + 1e-5f);
    float* Co = g_mixt + (size_t)bq*(G_*32*CG_) + g*(32*CG_);
    #pragma unroll
    for (int j = 0; j < 8; j++)
        Co[o*64 + e0 + j] = fmaxf((a2[j]-mu)*rstd, 0.f);
}

// ------------------ split-K reduce + bias + residual + LayerNorm ---------
__global__ void __launch_bounds__(256)
k_epilogue(const float* __restrict__ part, int nsplit,
           const float* __restrict__ bias, const float* __restrict__ query,
           const float* __restrict__ gamma, const float* __restrict__ beta,
           float* __restrict__ out) {
    __shared__ float red[16];
    int m = blockIdx.x, d = threadIdx.x;
    float v = bias[d] + query[m*D_ + d];
    for (int s = 0; s < nsplit; s++) v += part[(size_t)(s*BQ_ + m)*D_ + d];
    float s1 = v, q1 = v*v;
    blockReduce2(s1, q1, red);
    float mu = s1 * (1.f/256.f);
    float var = fmaxf(q1 * (1.f/256.f) - mu*mu, 0.f);
    out[m*D_ + d] = (v - mu) * rsqrtf(var + 1e-5f) * gamma[d] + beta[d];
}

// ------------------ launch ------------------------------------------------
static float* sym(const void* s) {
    void* p = nullptr;
    cudaGetSymbolAddress(&p, s);
    return (float*)p;
}

extern "C" void kernel_launch(void* const* d_in, const int* in_sizes, int n_in,
                              void* d_out, int out_size) {
    const float* feat0 = (const float*)d_in[0];
    const float* feat1 = (const float*)d_in[1];
    const float* feat2 = (const float*)d_in[2];
    const float* feat3 = (const float*)d_in[3];
    const float* boxes = (const float*)d_in[4];
    const float* squer = (const float*)d_in[5];
    const float* tquer = (const float*)d_in[6];
    const float* W_off = (const float*)d_in[7];
    const float* b_off = (const float*)d_in[8];
    const float* W_ps  = (const float*)d_in[9];
    const float* b_ps  = (const float*)d_in[10];
    const float* Wo_s  = (const float*)d_in[11];
    const float* bo_s  = (const float*)d_in[12];
    const float* g_s   = (const float*)d_in[13];
    const float* be_s  = (const float*)d_in[14];
    const float* W_pt  = (const float*)d_in[15];
    const float* b_pt  = (const float*)d_in[16];
    const float* Wo_t  = (const float*)d_in[17];
    const float* bo_t  = (const float*)d_in[18];
    const float* g_t   = (const float*)d_in[19];
    const float* be_t  = (const float*)d_in[20];
    float* out = (float*)d_out;

    float* p_ftr0 = sym(g_ftr0); float* p_ftr1 = sym(g_ftr1);
    float* p_ftr2 = sym(g_ftr2); float* p_ftr3 = sym(g_ftr3);
    float* p_off  = sym(g_off);
    float* p_ps   = sym(g_ps);   float* p_pt   = sym(g_pt);
    float* p_mixs = sym(g_mixs); float* p_mixt = sym(g_mixt);
    float* p_parts = sym(g_part_s); float* p_partt = sym(g_part_t);

    // Launch order chosen so the big W_ps GEMM sits at my-index-3, the slot
    // the fixed ncu window (-s 5 -c 1) has been landing on.
    k_transpose<<<dim3(2, 8, B_*64), 256>>>(feat0, p_ftr0, 64, 64);   // 0
    k_transpose<<<dim3(1, 8, B_*32), 256>>>(feat1, p_ftr1, 32, 32);   // 1
    k_transpose<<<dim3(1, 8, B_*16), 256>>>(feat2, p_ftr2, 16, 16);   // 2
    k_gemm<<<dim3(NS_/64, 4, 1), 256>>>(squer, W_ps, b_ps, p_ps, BQ_, NS_, D_, D_);  // 3 <- profiled
    k_transpose<<<dim3(1, 8, B_*8 ), 256>>>(feat3, p_ftr3, 8, 8);     // 4
    k_gemm<<<dim3(384/64, 4, 1), 256>>>(squer, W_off, b_off, p_off, BQ_, 384, D_, D_);
    k_gemm<<<dim3(NT_/64, 4, 1), 256>>>(tquer, W_pt,  b_pt,  p_pt,  BQ_, NT_, D_, D_);

    // sampling (fused T-mean and SP-mean)
    k_sample<<<BQ_*G_, 256>>>(boxes);

    // adaptive mixing
    k_mix_s<<<BQ_*G_, 256>>>();
    k_mix_t<<<BQ_*G_, 256>>>();

    // output GEMMs (deterministic split-K)
    k_gemm<<<dim3(D_/64, 4, NSPLIT_S), 256>>>(p_mixs, Wo_s, nullptr, p_parts, BQ_, D_, NS_,       NS_/NSPLIT_S);
    k_gemm<<<dim3(D_/64, 4, NSPLIT_T), 256>>>(p_mixt, Wo_t, nullptr, p_partt, BQ_, D_, G_*32*CG_, (G_*32*CG_)/NSPLIT_T);

    // reduce + residual + LN
    k_epilogue<<<BQ_, 256>>>(p_parts, NSPLIT_S, bo_s, squer, g_s, be_s, out);
    k_epilogue<<<BQ_, 256>>>(p_partt, NSPLIT_T, bo_t, tquer, g_t, be_t, out + BQ_*D_);
}